// round 1
// baseline (speedup 1.0000x reference)
#include <cuda_runtime.h>
#include <cuda_bf16.h>

// Problem constants
#define NROWS 2048
#define DDIM  9216            // C*KH*KW = 1024*3*3
#define TDIM  32              // NROWS / 64 tiles per dimension
#define NPAIRBLOCKS 528       // TDIM*(TDIM+1)/2

// Device scratch (no allocations allowed)
__device__ float g_nf[(size_t)NROWS * DDIM];  // compact normalized rows
__device__ int   g_pos[NROWS];                // compact slot per row, -1 if inactive
__device__ int   g_k;                         // number of active rows
__device__ float g_sumsq;                     // accumulator for sum of squared corr

// ---------------------------------------------------------------------------
// Kernel 0: scan mask -> compact positions, active count, zero accumulator.
// One block, 1024 threads; each thread owns elements 2t and 2t+1.
// ---------------------------------------------------------------------------
__global__ void scan_mask_kernel(const float* __restrict__ mask) {
    __shared__ int s[1024];
    int t = threadIdx.x;
    int a0 = (mask[2 * t]     > 0.5f) ? 1 : 0;
    int a1 = (mask[2 * t + 1] > 0.5f) ? 1 : 0;
    int pair = a0 + a1;
    s[t] = pair;
    __syncthreads();
    // Hillis-Steele inclusive scan over 1024 pair-sums
    for (int off = 1; off < 1024; off <<= 1) {
        int v = s[t];
        if (t >= off) v += s[t - off];
        __syncthreads();
        s[t] = v;
        __syncthreads();
    }
    int base = s[t] - pair;  // exclusive prefix for this thread's pair
    g_pos[2 * t]     = a0 ? base : -1;
    g_pos[2 * t + 1] = a1 ? (base + a0) : -1;
    if (t == 1023) g_k = s[1023];
    if (t == 0)    g_sumsq = 0.0f;
}

// ---------------------------------------------------------------------------
// Kernel 1: per-row normalize and compact.
// One block per row, 256 threads. Row cached in registers (9 float4/thread).
// ---------------------------------------------------------------------------
__global__ void __launch_bounds__(256) normalize_kernel(const float* __restrict__ w) {
    int row = blockIdx.x;
    int pos = g_pos[row];
    if (pos < 0) return;

    int tid = threadIdx.x;
    const float4* src = (const float4*)(w + (size_t)row * DDIM);
    float4 v[9];  // 2304 float4 per row / 256 threads = 9
    float sum = 0.0f, sumsq = 0.0f;
#pragma unroll
    for (int i = 0; i < 9; i++) {
        v[i] = src[tid + i * 256];
        sum   += v[i].x + v[i].y + v[i].z + v[i].w;
        sumsq += v[i].x * v[i].x + v[i].y * v[i].y + v[i].z * v[i].z + v[i].w * v[i].w;
    }

    __shared__ float rs[256], rq[256];
    rs[tid] = sum; rq[tid] = sumsq;
    __syncthreads();
    for (int o = 128; o > 0; o >>= 1) {
        if (tid < o) { rs[tid] += rs[tid + o]; rq[tid] += rq[tid + o]; }
        __syncthreads();
    }
    __shared__ float s_mean, s_inv;
    if (tid == 0) {
        float mean = rs[0] * (1.0f / DDIM);
        float var  = fmaxf(rq[0] * (1.0f / DDIM) - mean * mean, 0.0f);
        float stdv = sqrtf(var);
        s_mean = mean;
        s_inv  = (stdv == 0.0f) ? 1.0f : (1.0f / stdv);
    }
    __syncthreads();
    float mean = s_mean, inv = s_inv;

    float4* dst = (float4*)(g_nf + (size_t)pos * DDIM);
#pragma unroll
    for (int i = 0; i < 9; i++) {
        float4 o;
        o.x = (v[i].x - mean) * inv;
        o.y = (v[i].y - mean) * inv;
        o.z = (v[i].z - mean) * inv;
        o.w = (v[i].w - mean) * inv;
        dst[tid + i * 256] = o;
    }
}

// ---------------------------------------------------------------------------
// Kernel 2: upper-triangular tiled Gram over compact rows + fused squared-sum.
// 64x64 tile per block, 256 threads, 4x4 micro-tile per thread (strided rows
// ty+16u / tx+16u so smem reads are conflict-free with odd pitch 17).
// ---------------------------------------------------------------------------
__global__ void __launch_bounds__(256) gram_kernel() {
    __shared__ float As[64][17];
    __shared__ float Bs[64][17];

    int k = g_k;
    int b = blockIdx.x;
    // decode b -> (bi, bj) with bi <= bj
    int bi = 0, rem = b;
    while (rem >= TDIM - bi) { rem -= TDIM - bi; bi++; }
    int bj = bi + rem;
    if (bj * 64 >= k) return;  // no valid j in this tile -> no pairs

    int tid = threadIdx.x;
    int tx = tid & 15;
    int ty = tid >> 4;
    int lkc  = tid & 15;   // loader: k-offset within 16-wide k-block
    int lrow = tid >> 4;   // loader: base row (0..15)

    const float* A0 = g_nf + (size_t)(bi * 64) * DDIM;
    const float* B0 = g_nf + (size_t)(bj * 64) * DDIM;
    int arows = min(64, k - bi * 64);
    int brows = min(64, k - bj * 64);

    float acc[4][4];
#pragma unroll
    for (int i = 0; i < 4; i++)
#pragma unroll
        for (int j = 0; j < 4; j++) acc[i][j] = 0.0f;

    for (int kb = 0; kb < DDIM; kb += 16) {
#pragma unroll
        for (int rr = 0; rr < 4; rr++) {
            int row = lrow + rr * 16;
            As[row][lkc] = (row < arows) ? A0[(size_t)row * DDIM + kb + lkc] : 0.0f;
            Bs[row][lkc] = (row < brows) ? B0[(size_t)row * DDIM + kb + lkc] : 0.0f;
        }
        __syncthreads();
#pragma unroll
        for (int kk = 0; kk < 16; kk++) {
            float a[4], bq[4];
#pragma unroll
            for (int u = 0; u < 4; u++) a[u]  = As[ty + u * 16][kk];
#pragma unroll
            for (int u = 0; u < 4; u++) bq[u] = Bs[tx + u * 16][kk];
#pragma unroll
            for (int i2 = 0; i2 < 4; i2++)
#pragma unroll
                for (int j2 = 0; j2 < 4; j2++)
                    acc[i2][j2] += a[i2] * bq[j2];
        }
        __syncthreads();
    }

    // fused masked squared-sum over strict upper triangle (compact indices)
    const float invD = 1.0f / (float)DDIM;
    float s = 0.0f;
#pragma unroll
    for (int i2 = 0; i2 < 4; i2++) {
        int gi = bi * 64 + ty + i2 * 16;
#pragma unroll
        for (int j2 = 0; j2 < 4; j2++) {
            int gj = bj * 64 + tx + j2 * 16;
            if (gi < gj && gj < k) {
                float c = acc[i2][j2] * invD;
                s += c * c;
            }
        }
    }

    __shared__ float red[256];
    red[tid] = s;
    __syncthreads();
    for (int o = 128; o > 0; o >>= 1) {
        if (tid < o) red[tid] += red[tid + o];
        __syncthreads();
    }
    if (tid == 0) atomicAdd(&g_sumsq, red[0]);
}

// ---------------------------------------------------------------------------
// Kernel 3: finalize loss = sumsq / (k*(k-1)/2), or 0 if no active pairs.
// ---------------------------------------------------------------------------
__global__ void finalize_kernel(float* __restrict__ out) {
    int k = g_k;
    long long np = (long long)k * (k - 1) / 2;
    out[0] = (np > 0) ? (g_sumsq / (float)np) : 0.0f;
}

extern "C" void kernel_launch(void* const* d_in, const int* in_sizes, int n_in,
                              void* d_out, int out_size) {
    const float* w    = (const float*)d_in[0];  // [2048,1024,3,3] fp32
    const float* mask = (const float*)d_in[1];  // [2048,1,1,1]   fp32
    float* out = (float*)d_out;

    scan_mask_kernel<<<1, 1024>>>(mask);
    normalize_kernel<<<NROWS, 256>>>(w);
    gram_kernel<<<NPAIRBLOCKS, 256>>>();
    finalize_kernel<<<1, 1>>>(out);
}

// round 2
// speedup vs baseline: 6.4701x; 6.4701x over previous
#include <cuda_runtime.h>
#include <cuda_bf16.h>
#include <cstdint>

// Problem constants
#define NROWS 2048
#define DDIM  9216            // C*KH*KW = 1024*3*3
#define BM    64              // gram tile (square)
#define BK    32
#define TDIM  (NROWS / BM)    // 32 tiles per dimension
#define NPAIRBLOCKS (TDIM * (TDIM + 1) / 2)   // 528
#define NIT   (DDIM / BK)     // 288 k-iterations

// Device scratch (no allocations allowed)
__device__ __align__(16) __nv_bfloat16 g_nf[(size_t)NROWS * DDIM];  // compact normalized rows (bf16)
__device__ int   g_pos[NROWS];   // compact slot per row, -1 if inactive
__device__ int   g_k;            // number of active rows
__device__ float g_sumsq;        // accumulator for sum of squared corr

// ---------------------------------------------------------------------------
// Kernel 0: scan mask -> compact positions, active count, zero accumulator.
// ---------------------------------------------------------------------------
__global__ void scan_mask_kernel(const float* __restrict__ mask) {
    __shared__ int s[1024];
    int t = threadIdx.x;
    int a0 = (mask[2 * t]     > 0.5f) ? 1 : 0;
    int a1 = (mask[2 * t + 1] > 0.5f) ? 1 : 0;
    int pair = a0 + a1;
    s[t] = pair;
    __syncthreads();
    for (int off = 1; off < 1024; off <<= 1) {
        int v = s[t];
        if (t >= off) v += s[t - off];
        __syncthreads();
        s[t] = v;
        __syncthreads();
    }
    int base = s[t] - pair;
    g_pos[2 * t]     = a0 ? base : -1;
    g_pos[2 * t + 1] = a1 ? (base + a0) : -1;
    if (t == 1023) g_k = s[1023];
    if (t == 0)    g_sumsq = 0.0f;
}

// ---------------------------------------------------------------------------
// Kernel 1: per-row normalize, compact, convert to bf16.
// One block per row, 256 threads. Row cached in registers (9 float4/thread).
// ---------------------------------------------------------------------------
__global__ void __launch_bounds__(256) normalize_kernel(const float* __restrict__ w) {
    int row = blockIdx.x;
    int pos = g_pos[row];
    if (pos < 0) return;

    int tid = threadIdx.x;
    const float4* src = (const float4*)(w + (size_t)row * DDIM);
    float4 v[9];
    float sum = 0.0f, sumsq = 0.0f;
#pragma unroll
    for (int i = 0; i < 9; i++) {
        v[i] = src[tid + i * 256];
        sum   += v[i].x + v[i].y + v[i].z + v[i].w;
        sumsq += v[i].x * v[i].x + v[i].y * v[i].y + v[i].z * v[i].z + v[i].w * v[i].w;
    }

    __shared__ float rs[256], rq[256];
    rs[tid] = sum; rq[tid] = sumsq;
    __syncthreads();
    for (int o = 128; o > 0; o >>= 1) {
        if (tid < o) { rs[tid] += rs[tid + o]; rq[tid] += rq[tid + o]; }
        __syncthreads();
    }
    __shared__ float s_mean, s_inv;
    if (tid == 0) {
        float mean = rs[0] * (1.0f / DDIM);
        float var  = fmaxf(rq[0] * (1.0f / DDIM) - mean * mean, 0.0f);
        float stdv = sqrtf(var);
        s_mean = mean;
        s_inv  = (stdv == 0.0f) ? 1.0f : (1.0f / stdv);
    }
    __syncthreads();
    float mean = s_mean, inv = s_inv;

    uint2* dst = (uint2*)(g_nf + (size_t)pos * DDIM);
#pragma unroll
    for (int i = 0; i < 9; i++) {
        __nv_bfloat162 lo = __floats2bfloat162_rn((v[i].x - mean) * inv, (v[i].y - mean) * inv);
        __nv_bfloat162 hi = __floats2bfloat162_rn((v[i].z - mean) * inv, (v[i].w - mean) * inv);
        uint2 o;
        o.x = *(uint32_t*)&lo;
        o.y = *(uint32_t*)&hi;
        dst[tid + i * 256] = o;
    }
}

// ---------------------------------------------------------------------------
// Kernel 2: upper-triangular 64x64 bf16 Gram via mma.sync + fused squared-sum.
// 128 threads (4 warps, 2x2 warp grid, 32x32 per warp).
// cp.async double-buffered smem, XOR-swizzled for conflict-free ldmatrix.
// ---------------------------------------------------------------------------
__device__ __forceinline__ void cp_async16(uint32_t dst, const void* src, int src_size) {
    asm volatile("cp.async.cg.shared.global [%0], [%1], 16, %2;\n"
                 :: "r"(dst), "l"(src), "r"(src_size));
}
__device__ __forceinline__ void cp_commit() { asm volatile("cp.async.commit_group;\n"); }

// smem layout per stage: 64 rows x 64 bytes (32 bf16). group g (16B) of row r is
// stored at group (g ^ ((r>>1)&3)) -> 8 distinct 16B chunks mod 128B per octet.
__device__ __forceinline__ uint32_t sw_off(int r, int g) {
    return (uint32_t)(r * 64 + ((g ^ ((r >> 1) & 3)) << 4));
}

__global__ void __launch_bounds__(128) gram_kernel() {
    __shared__ __align__(16) char smem[2 * 2 * 4096];  // [stage][A|B][64*64B]

    int k = g_k;
    int b = blockIdx.x;
    int bi = 0, rem = b;
    while (rem >= TDIM - bi) { rem -= TDIM - bi; bi++; }
    int bj = bi + rem;
    if (bj * BM >= k) return;

    int tid  = threadIdx.x;
    int lane = tid & 31;
    int warp = tid >> 5;
    int wm = warp & 1, wn = warp >> 1;

    int arows = min(BM, k - bi * BM);
    int brows = min(BM, k - bj * BM);
    const __nv_bfloat16* A0 = g_nf + (size_t)(bi * BM) * DDIM;
    const __nv_bfloat16* B0 = g_nf + (size_t)(bj * BM) * DDIM;

    uint32_t sbase = (uint32_t)__cvta_generic_to_shared(smem);
    // loader: 2 chunks each for A and B; chunk = tid*2 + c -> row = chunk>>2, grp = chunk&3
    int lr = tid >> 1;            // row for both chunks
    int lg0 = (tid & 1) * 2;      // groups lg0, lg0+1

    float acc[2][4][4];
#pragma unroll
    for (int mt = 0; mt < 2; mt++)
#pragma unroll
        for (int nt = 0; nt < 4; nt++)
#pragma unroll
            for (int e = 0; e < 4; e++) acc[mt][nt][e] = 0.0f;

    // ---- load one stage
    auto load_stage = [&](int s, int kb) {
        uint32_t aBase = sbase + s * 4096;
        uint32_t bBase = sbase + 8192 + s * 4096;
        const __nv_bfloat16* ga = A0 + (size_t)lr * DDIM + kb + lg0 * 8;
        const __nv_bfloat16* gb = B0 + (size_t)lr * DDIM + kb + lg0 * 8;
        int za = (lr < arows) ? 16 : 0;
        int zb = (lr < brows) ? 16 : 0;
        cp_async16(aBase + sw_off(lr, lg0),     ga,     za);
        cp_async16(aBase + sw_off(lr, lg0 + 1), ga + 8, za);
        cp_async16(bBase + sw_off(lr, lg0),     gb,     zb);
        cp_async16(bBase + sw_off(lr, lg0 + 1), gb + 8, zb);
    };

    load_stage(0, 0);
    cp_commit();

    for (int it = 0; it < NIT; it++) {
        if (it + 1 < NIT) {
            load_stage((it + 1) & 1, (it + 1) * BK);
            cp_commit();
            asm volatile("cp.async.wait_group 1;\n");
        } else {
            asm volatile("cp.async.wait_group 0;\n");
        }
        __syncthreads();

        int s = it & 1;
        uint32_t aBase = sbase + s * 4096;
        uint32_t bBase = sbase + 8192 + s * 4096;

#pragma unroll
        for (int kk = 0; kk < 2; kk++) {   // two k16 steps per BK=32
            uint32_t af[2][4];
            uint32_t bf[4][2];
#pragma unroll
            for (int mt = 0; mt < 2; mt++) {
                int r = wm * 32 + mt * 16 + (lane & 15);
                int g = kk * 2 + (lane >> 4);
                uint32_t addr = aBase + sw_off(r, g);
                asm volatile("ldmatrix.sync.aligned.m8n8.x4.shared.b16 {%0,%1,%2,%3}, [%4];\n"
                             : "=r"(af[mt][0]), "=r"(af[mt][1]), "=r"(af[mt][2]), "=r"(af[mt][3])
                             : "r"(addr));
            }
#pragma unroll
            for (int nt = 0; nt < 4; nt++) {
                int r = wn * 32 + nt * 8 + (lane & 7);
                int g = kk * 2 + ((lane >> 3) & 1);
                uint32_t addr = bBase + sw_off(r, g);
                asm volatile("ldmatrix.sync.aligned.m8n8.x2.shared.b16 {%0,%1}, [%2];\n"
                             : "=r"(bf[nt][0]), "=r"(bf[nt][1])
                             : "r"(addr));
            }
#pragma unroll
            for (int mt = 0; mt < 2; mt++)
#pragma unroll
                for (int nt = 0; nt < 4; nt++) {
                    asm volatile(
                        "mma.sync.aligned.m16n8k16.row.col.f32.bf16.bf16.f32 "
                        "{%0,%1,%2,%3}, {%4,%5,%6,%7}, {%8,%9}, {%0,%1,%2,%3};\n"
                        : "+f"(acc[mt][nt][0]), "+f"(acc[mt][nt][1]),
                          "+f"(acc[mt][nt][2]), "+f"(acc[mt][nt][3])
                        : "r"(af[mt][0]), "r"(af[mt][1]), "r"(af[mt][2]), "r"(af[mt][3]),
                          "r"(bf[nt][0]), "r"(bf[nt][1]));
                }
        }
        __syncthreads();
    }

    // fused squared-sum over strict upper triangle (padded rows are zeros)
    const float invD = 1.0f / (float)DDIM;
    float ssum = 0.0f;
#pragma unroll
    for (int mt = 0; mt < 2; mt++)
#pragma unroll
        for (int nt = 0; nt < 4; nt++)
#pragma unroll
            for (int e = 0; e < 4; e++) {
                int gi = bi * BM + wm * 32 + mt * 16 + (lane >> 2) + ((e >> 1) << 3);
                int gj = bj * BM + wn * 32 + nt * 8 + ((lane & 3) << 1) + (e & 1);
                if (gi < gj) {
                    float c = acc[mt][nt][e] * invD;
                    ssum += c * c;
                }
            }

    __shared__ float red[128];
    red[tid] = ssum;
    __syncthreads();
    for (int o = 64; o > 0; o >>= 1) {
        if (tid < o) red[tid] += red[tid + o];
        __syncthreads();
    }
    if (tid == 0) atomicAdd(&g_sumsq, red[0]);
}

// ---------------------------------------------------------------------------
// Kernel 3: finalize loss = sumsq / (k*(k-1)/2), or 0 if no active pairs.
// ---------------------------------------------------------------------------
__global__ void finalize_kernel(float* __restrict__ out) {
    int k = g_k;
    long long np = (long long)k * (k - 1) / 2;
    out[0] = (np > 0) ? (g_sumsq / (float)np) : 0.0f;
}

extern "C" void kernel_launch(void* const* d_in, const int* in_sizes, int n_in,
                              void* d_out, int out_size) {
    const float* w    = (const float*)d_in[0];  // [2048,1024,3,3] fp32
    const float* mask = (const float*)d_in[1];  // [2048,1,1,1]   fp32
    float* out = (float*)d_out;

    scan_mask_kernel<<<1, 1024>>>(mask);
    normalize_kernel<<<NROWS, 256>>>(w);
    gram_kernel<<<NPAIRBLOCKS, 128>>>();
    finalize_kernel<<<1, 1>>>(out);
}

// round 3
// speedup vs baseline: 9.0883x; 1.4047x over previous
#include <cuda_runtime.h>
#include <cuda_bf16.h>
#include <cstdint>

// Problem constants
#define NROWS 2048
#define DDIM  9216            // C*KH*KW = 1024*3*3
#define BM    64              // gram tile (square)
#define BK    64              // k-slice per pipeline stage
#define TDIM  (NROWS / BM)    // 32 tiles per dimension
#define NPAIRBLOCKS (TDIM * (TDIM + 1) / 2)   // 528
#define NIT   (DDIM / BK)     // 144 k-iterations
#define STAGES 4
#define STAGE_BYTES 8192      // 64 rows * 128 B
#define SMEM_BYTES (2 * STAGES * STAGE_BYTES) // 64 KB

// Device scratch (no allocations allowed)
__device__ __align__(16) __nv_bfloat16 g_nf[(size_t)NROWS * DDIM];
__device__ int          g_pos[NROWS];
__device__ int          g_k;
__device__ float        g_sumsq;
__device__ unsigned int g_done = 0;

// ---------------------------------------------------------------------------
// Kernel 0: scan mask -> compact positions, active count, reset accumulators.
// ---------------------------------------------------------------------------
__global__ void scan_mask_kernel(const float* __restrict__ mask) {
    __shared__ int s[1024];
    int t = threadIdx.x;
    int a0 = (mask[2 * t]     > 0.5f) ? 1 : 0;
    int a1 = (mask[2 * t + 1] > 0.5f) ? 1 : 0;
    int pair = a0 + a1;
    s[t] = pair;
    __syncthreads();
    for (int off = 1; off < 1024; off <<= 1) {
        int v = s[t];
        if (t >= off) v += s[t - off];
        __syncthreads();
        s[t] = v;
        __syncthreads();
    }
    int base = s[t] - pair;
    g_pos[2 * t]     = a0 ? base : -1;
    g_pos[2 * t + 1] = a1 ? (base + a0) : -1;
    if (t == 1023) g_k = s[1023];
    if (t == 0) { g_sumsq = 0.0f; g_done = 0u; }
}

// ---------------------------------------------------------------------------
// Kernel 1: per-row normalize, compact, convert to bf16.
// ---------------------------------------------------------------------------
__global__ void __launch_bounds__(256) normalize_kernel(const float* __restrict__ w) {
    int row = blockIdx.x;
    int pos = g_pos[row];
    if (pos < 0) return;

    int tid = threadIdx.x;
    const float4* src = (const float4*)(w + (size_t)row * DDIM);
    float4 v[9];
    float sum = 0.0f, sumsq = 0.0f;
#pragma unroll
    for (int i = 0; i < 9; i++) {
        v[i] = src[tid + i * 256];
        sum   += v[i].x + v[i].y + v[i].z + v[i].w;
        sumsq += v[i].x * v[i].x + v[i].y * v[i].y + v[i].z * v[i].z + v[i].w * v[i].w;
    }

    __shared__ float rs[256], rq[256];
    rs[tid] = sum; rq[tid] = sumsq;
    __syncthreads();
    for (int o = 128; o > 0; o >>= 1) {
        if (tid < o) { rs[tid] += rs[tid + o]; rq[tid] += rq[tid + o]; }
        __syncthreads();
    }
    __shared__ float s_mean, s_inv;
    if (tid == 0) {
        float mean = rs[0] * (1.0f / DDIM);
        float var  = fmaxf(rq[0] * (1.0f / DDIM) - mean * mean, 0.0f);
        float stdv = sqrtf(var);
        s_mean = mean;
        s_inv  = (stdv == 0.0f) ? 1.0f : (1.0f / stdv);
    }
    __syncthreads();
    float mean = s_mean, inv = s_inv;

    uint2* dst = (uint2*)(g_nf + (size_t)pos * DDIM);
#pragma unroll
    for (int i = 0; i < 9; i++) {
        __nv_bfloat162 lo = __floats2bfloat162_rn((v[i].x - mean) * inv, (v[i].y - mean) * inv);
        __nv_bfloat162 hi = __floats2bfloat162_rn((v[i].z - mean) * inv, (v[i].w - mean) * inv);
        uint2 o;
        o.x = *(uint32_t*)&lo;
        o.y = *(uint32_t*)&hi;
        dst[tid + i * 256] = o;
    }
}

// ---------------------------------------------------------------------------
// Kernel 2: upper-triangular 64x64 bf16 Gram via mma.sync, 8 warps,
// 4-stage cp.async pipeline, fused squared-sum + fused finalize.
// ---------------------------------------------------------------------------
__device__ __forceinline__ void cp_async16(uint32_t dst, const void* src, int src_size) {
    asm volatile("cp.async.cg.shared.global [%0], [%1], 16, %2;\n"
                 :: "r"(dst), "l"(src), "r"(src_size));
}
__device__ __forceinline__ void cp_commit() { asm volatile("cp.async.commit_group;\n"); }

// row pitch 128 B (64 bf16). 16B group g of row r stored at group g ^ (r & 7).
__device__ __forceinline__ uint32_t sw_off(int r, int g) {
    return (uint32_t)(r * 128 + ((g ^ (r & 7)) << 4));
}

__global__ void __launch_bounds__(256) gram_kernel(float* __restrict__ out) {
    extern __shared__ __align__(16) char smem[];

    int k = g_k;
    int b = blockIdx.x;
    int bi = 0, rem = b;
    while (rem >= TDIM - bi) { rem -= TDIM - bi; bi++; }
    int bj = bi + rem;

    int tid  = threadIdx.x;
    int lane = tid & 31;
    int warp = tid >> 5;

    if (bj * BM < k) {   // tile has at least one valid pair
        int wm = warp & 1;          // 0..1 : 32-row strip
        int wn = warp >> 1;         // 0..3 : 16-col strip

        int arows = min(BM, k - bi * BM);
        int brows = min(BM, k - bj * BM);
        const __nv_bfloat16* A0 = g_nf + (size_t)(bi * BM) * DDIM;
        const __nv_bfloat16* B0 = g_nf + (size_t)(bj * BM) * DDIM;

        uint32_t sb = (uint32_t)__cvta_generic_to_shared(smem);

        // loader mapping: thread -> row (tid>>2), two 16B groups
        int lrow = tid >> 2;
        int lg0  = (tid & 3) * 2;
        const __nv_bfloat16* gA = A0 + (size_t)lrow * DDIM + lg0 * 8;
        const __nv_bfloat16* gB = B0 + (size_t)lrow * DDIM + lg0 * 8;
        int za = (lrow < arows) ? 16 : 0;
        int zb = (lrow < brows) ? 16 : 0;
        uint32_t swA0 = sw_off(lrow, lg0), swA1 = sw_off(lrow, lg0 + 1);

        float acc[2][2][4];
#pragma unroll
        for (int mt = 0; mt < 2; mt++)
#pragma unroll
            for (int nt = 0; nt < 2; nt++)
#pragma unroll
                for (int e = 0; e < 4; e++) acc[mt][nt][e] = 0.0f;

        auto load_stage = [&](int s, int kb) {
            uint32_t aB = sb + s * STAGE_BYTES;
            uint32_t bB = sb + STAGES * STAGE_BYTES + s * STAGE_BYTES;
            cp_async16(aB + swA0, gA + kb,     za);
            cp_async16(aB + swA1, gA + kb + 8, za);
            cp_async16(bB + swA0, gB + kb,     zb);
            cp_async16(bB + swA1, gB + kb + 8, zb);
        };

        // prologue: 3 stages in flight
#pragma unroll
        for (int s = 0; s < STAGES - 1; s++) { load_stage(s, s * BK); cp_commit(); }

        // per-warp fragment row bases (fixed across iterations)
        int raBase = wm * 32 + (lane & 15);            // A rows, mt adds +16
        int gaHalf = lane >> 4;                        // A k-half select
        int rbRow  = wn * 16 + (lane & 7) + ((lane >> 4) << 3);  // B rows
        int gbHalf = (lane >> 3) & 1;                  // B k-half select

        for (int it = 0; it < NIT; it++) {
            asm volatile("cp.async.wait_group %0;\n" :: "n"(STAGES - 2));
            __syncthreads();

            if (it + STAGES - 1 < NIT) load_stage((it + STAGES - 1) & (STAGES - 1),
                                                  (it + STAGES - 1) * BK);
            cp_commit();   // empty group in tail keeps wait arithmetic uniform

            int s = it & (STAGES - 1);
            uint32_t aB = sb + s * STAGE_BYTES;
            uint32_t bB = sb + STAGES * STAGE_BYTES + s * STAGE_BYTES;

#pragma unroll
            for (int kk = 0; kk < 4; kk++) {           // four k16 steps per BK=64
                uint32_t af[2][4];
                uint32_t bf[4];
#pragma unroll
                for (int mt = 0; mt < 2; mt++) {
                    int r = raBase + mt * 16;
                    uint32_t addr = aB + (uint32_t)(r * 128 + (((kk * 2 + gaHalf) ^ (r & 7)) << 4));
                    asm volatile("ldmatrix.sync.aligned.m8n8.x4.shared.b16 {%0,%1,%2,%3}, [%4];\n"
                                 : "=r"(af[mt][0]), "=r"(af[mt][1]), "=r"(af[mt][2]), "=r"(af[mt][3])
                                 : "r"(addr));
                }
                {
                    int r = rbRow;
                    uint32_t addr = bB + (uint32_t)(r * 128 + (((kk * 2 + gbHalf) ^ (r & 7)) << 4));
                    asm volatile("ldmatrix.sync.aligned.m8n8.x4.shared.b16 {%0,%1,%2,%3}, [%4];\n"
                                 : "=r"(bf[0]), "=r"(bf[1]), "=r"(bf[2]), "=r"(bf[3])
                                 : "r"(addr));
                }
#pragma unroll
                for (int mt = 0; mt < 2; mt++)
#pragma unroll
                    for (int nt = 0; nt < 2; nt++) {
                        asm volatile(
                            "mma.sync.aligned.m16n8k16.row.col.f32.bf16.bf16.f32 "
                            "{%0,%1,%2,%3}, {%4,%5,%6,%7}, {%8,%9}, {%0,%1,%2,%3};\n"
                            : "+f"(acc[mt][nt][0]), "+f"(acc[mt][nt][1]),
                              "+f"(acc[mt][nt][2]), "+f"(acc[mt][nt][3])
                            : "r"(af[mt][0]), "r"(af[mt][1]), "r"(af[mt][2]), "r"(af[mt][3]),
                              "r"(bf[nt * 2]), "r"(bf[nt * 2 + 1]));
                    }
            }
        }

        // fused squared-sum over strict upper triangle (padded rows are zeros)
        const float invD = 1.0f / (float)DDIM;
        float ssum = 0.0f;
#pragma unroll
        for (int mt = 0; mt < 2; mt++)
#pragma unroll
            for (int nt = 0; nt < 2; nt++)
#pragma unroll
                for (int e = 0; e < 4; e++) {
                    int gi = bi * BM + wm * 32 + mt * 16 + (lane >> 2) + ((e >> 1) << 3);
                    int gj = bj * BM + wn * 16 + nt * 8 + ((lane & 3) << 1) + (e & 1);
                    if (gi < gj) {
                        float c = acc[mt][nt][e] * invD;
                        ssum += c * c;
                    }
                }

        // warp reduce + one atomic per warp
#pragma unroll
        for (int o = 16; o > 0; o >>= 1)
            ssum += __shfl_xor_sync(0xffffffffu, ssum, o);
        if (lane == 0) atomicAdd(&g_sumsq, ssum);
    }

    // completion counter: last of all NPAIRBLOCKS blocks finalizes the loss
    __syncthreads();
    if (tid == 0) {
        __threadfence();
        unsigned int prev = atomicAdd(&g_done, 1u);
        if (prev == NPAIRBLOCKS - 1) {
            float total = atomicAdd(&g_sumsq, 0.0f);   // ordered read
            long long np = (long long)k * (k - 1) / 2;
            out[0] = (np > 0) ? (total / (float)np) : 0.0f;
        }
    }
}

extern "C" void kernel_launch(void* const* d_in, const int* in_sizes, int n_in,
                              void* d_out, int out_size) {
    const float* w    = (const float*)d_in[0];  // [2048,1024,3,3] fp32
    const float* mask = (const float*)d_in[1];  // [2048,1,1,1]   fp32
    float* out = (float*)d_out;

    static bool attr_set = false;
    if (!attr_set) {
        cudaFuncSetAttribute(gram_kernel,
                             cudaFuncAttributeMaxDynamicSharedMemorySize, SMEM_BYTES);
        attr_set = true;
    }

    scan_mask_kernel<<<1, 1024>>>(mask);
    normalize_kernel<<<NROWS, 256>>>(w);
    gram_kernel<<<NPAIRBLOCKS, 256, SMEM_BYTES>>>(out);
}

// round 6
// speedup vs baseline: 15.7708x; 1.7353x over previous
#include <cuda_runtime.h>
#include <cuda_bf16.h>
#include <cstdint>

// Problem constants
#define NROWS 2048
#define DDIM  9216             // C*KH*KW
#define TBM   128              // gram tile M = N = 128
#define T16   (NROWS / TBM)    // 16 tiles per dim (max)
#define NPAIR (T16 * (T16 + 1) / 2)   // 136 tile-pairs
#define SPLITS 4
#define KCH   (DDIM / SPLITS)  // 2304 k-elems per split
#define BK    32               // k-elems per pipeline stage
#define NIT   (KCH / BK)       // 72 iterations
#define STAGES 4
#define STAGE_BYTES (2 * TBM * 64)          // A(8KB)+B(8KB) = 16 KB
#define DSMEM_BYTES (STAGES * STAGE_BYTES)  // 64 KB

// Device scratch (no allocations allowed)
__device__ __align__(16) __nv_bfloat16 g_nf[(size_t)NROWS * DDIM];
__device__ int      g_pos[NROWS];
__device__ int      g_k;
__device__ float    g_sumsq;
__device__ unsigned g_tile_cnt[NPAIR];
__device__ unsigned g_pairs_done;
__device__ float    g_part[NPAIR * SPLITS][TBM * TBM];  // split-K partial tiles

// ---------------- helpers ----------------
__device__ __forceinline__ void cp_async16(uint32_t dst, const void* src, int src_size) {
    asm volatile("cp.async.cg.shared.global [%0], [%1], 16, %2;\n"
                 :: "r"(dst), "l"(src), "r"(src_size));
}
__device__ __forceinline__ void cp_commit() { asm volatile("cp.async.commit_group;\n"); }

// row pitch 64 B (32 bf16). 16B group g of row r stored at group g ^ ((r>>1)&3):
// conflict-free for 8-row ldmatrix reads at this pitch.
__device__ __forceinline__ uint32_t sw_off(int r, int g) {
    return (uint32_t)(r * 64 + ((g ^ ((r >> 1) & 3)) << 4));
}

// ---------------------------------------------------------------------------
// Kernel 0: warp-shuffle scan of mask -> compact positions, k, reset counters.
// ---------------------------------------------------------------------------
__global__ void scan_mask_kernel(const float* __restrict__ mask, float* __restrict__ out) {
    __shared__ int wsum[32];
    int t = threadIdx.x;
    int a0 = (mask[2 * t]     > 0.5f) ? 1 : 0;
    int a1 = (mask[2 * t + 1] > 0.5f) ? 1 : 0;
    int pair = a0 + a1;
    int lane = t & 31, wid = t >> 5;
    const unsigned full = 0xffffffffu;
    int incl = pair;
#pragma unroll
    for (int o = 1; o < 32; o <<= 1) {
        int v = __shfl_up_sync(full, incl, o);
        if (lane >= o) incl += v;
    }
    if (lane == 31) wsum[wid] = incl;
    __syncthreads();
    if (wid == 0) {
        int iv = wsum[lane];
#pragma unroll
        for (int o = 1; o < 32; o <<= 1) {
            int u = __shfl_up_sync(full, iv, o);
            if (lane >= o) iv += u;
        }
        wsum[lane] = iv;
    }
    __syncthreads();
    int offs  = (wid > 0) ? wsum[wid - 1] : 0;
    int total = wsum[31];
    int base  = offs + incl - pair;
    g_pos[2 * t]     = a0 ? base : -1;
    g_pos[2 * t + 1] = a1 ? (base + a0) : -1;
    if (t < NPAIR) g_tile_cnt[t] = 0u;
    if (t == 0) {
        g_k = total; g_sumsq = 0.0f; g_pairs_done = 0u;
        if (total < 2) out[0] = 0.0f;   // no pairs -> loss 0
    }
}

// ---------------------------------------------------------------------------
// Kernel 1: per-row normalize, compact, convert to bf16.
// ---------------------------------------------------------------------------
__global__ void __launch_bounds__(256) normalize_kernel(const float* __restrict__ w) {
    int row = blockIdx.x;
    int pos = g_pos[row];
    if (pos < 0) return;

    int tid = threadIdx.x;
    const float4* src = (const float4*)(w + (size_t)row * DDIM);
    float4 v[9];
    float sum = 0.0f, sumsq = 0.0f;
#pragma unroll
    for (int i = 0; i < 9; i++) {
        v[i] = src[tid + i * 256];
        sum   += v[i].x + v[i].y + v[i].z + v[i].w;
        sumsq += v[i].x * v[i].x + v[i].y * v[i].y + v[i].z * v[i].z + v[i].w * v[i].w;
    }

    __shared__ float rs[256], rq[256];
    rs[tid] = sum; rq[tid] = sumsq;
    __syncthreads();
    for (int o = 128; o > 0; o >>= 1) {
        if (tid < o) { rs[tid] += rs[tid + o]; rq[tid] += rq[tid + o]; }
        __syncthreads();
    }
    __shared__ float s_mean, s_inv;
    if (tid == 0) {
        float mean = rs[0] * (1.0f / DDIM);
        float var  = fmaxf(rq[0] * (1.0f / DDIM) - mean * mean, 0.0f);
        float stdv = sqrtf(var);
        s_mean = mean;
        s_inv  = (stdv == 0.0f) ? 1.0f : (1.0f / stdv);
    }
    __syncthreads();
    float mean = s_mean, inv = s_inv;

    uint2* dst = (uint2*)(g_nf + (size_t)pos * DDIM);
#pragma unroll
    for (int i = 0; i < 9; i++) {
        __nv_bfloat162 lo = __floats2bfloat162_rn((v[i].x - mean) * inv, (v[i].y - mean) * inv);
        __nv_bfloat162 hi = __floats2bfloat162_rn((v[i].z - mean) * inv, (v[i].w - mean) * inv);
        uint2 o;
        o.x = *(uint32_t*)&lo;
        o.y = *(uint32_t*)&hi;
        dst[tid + i * 256] = o;
    }
}

// ---------------------------------------------------------------------------
// Kernel 2: 128x128 bf16 Gram tile via mma.sync, split-K=4, 8 warps
// (32x64 per warp -> 16 independent MMAs per k16 step), 4-stage cp.async ring.
// Partial tiles stored per split; last split squares + accumulates + finalizes.
// ---------------------------------------------------------------------------
__global__ void __launch_bounds__(256, 1) gram_kernel(float* __restrict__ out) {
    extern __shared__ __align__(16) char smem[];
    __shared__ float s_red[8];
    __shared__ unsigned s_prev;

    int k = g_k;
    int blk = blockIdx.x;
    int pair = blk >> 2;
    int split = blk & 3;
    int bi = 0, rem = pair;
    while (rem >= T16 - bi) { rem -= T16 - bi; bi++; }
    int bj = bi + rem;
    if (bj * TBM >= k) return;   // inactive tile

    int tid = threadIdx.x, lane = tid & 31, warp = tid >> 5;
    int wm = warp & 3;   // 0..3 : 32-row strip
    int wn = warp >> 2;  // 0..1 : 64-col strip

    int arows = min(TBM, k - bi * TBM);
    int brows = min(TBM, k - bj * TBM);

    uint32_t sb = (uint32_t)__cvta_generic_to_shared(smem);

    // loader: threads 0-127 -> A row tid, threads 128-255 -> B row tid-128.
    // each thread cp.asyncs 4 x 16B = one 64B stage-row.
    int lrow = tid & 127;
    bool isB = tid >= 128;
    int rowsLim = isB ? brows : arows;
    const __nv_bfloat16* gsrc = g_nf
        + (size_t)((isB ? bj : bi) * TBM + lrow) * DDIM + split * KCH;
    int zfill = (lrow < rowsLim) ? 16 : 0;
    uint32_t sbias = isB ? (uint32_t)(TBM * 64) : 0u;   // B half of stage
    uint32_t so[4];
#pragma unroll
    for (int g = 0; g < 4; g++) so[g] = sbias + sw_off(lrow, g);

    auto load_stage = [&](int slot, int kb) {
        uint32_t st = sb + slot * STAGE_BYTES;
#pragma unroll
        for (int g = 0; g < 4; g++)
            cp_async16(st + so[g], gsrc + kb + g * 8, zfill);
    };

    float acc[2][8][4];
#pragma unroll
    for (int mt = 0; mt < 2; mt++)
#pragma unroll
        for (int n = 0; n < 8; n++)
#pragma unroll
            for (int e = 0; e < 4; e++) acc[mt][n][e] = 0.0f;

    // prologue: 3 stages in flight
#pragma unroll
    for (int s = 0; s < STAGES - 1; s++) { load_stage(s, s * BK); cp_commit(); }

    // fixed per-warp fragment addressing
    int raBase = wm * 32 + (lane & 15);                 // A rows; mt adds +16
    int gaSel  = lane >> 4;                             // A k-half within k16
    int rbBase = wn * 64 + (lane & 7) + ((lane >> 4) << 3);  // B rows; nt adds +16
    int gbSel  = (lane >> 3) & 1;                       // B k-half within k16

    for (int it = 0; it < NIT; it++) {
        asm volatile("cp.async.wait_group %0;\n" :: "n"(STAGES - 2));
        __syncthreads();

        if (it + STAGES - 1 < NIT)
            load_stage((it + STAGES - 1) & (STAGES - 1), (it + STAGES - 1) * BK);
        cp_commit();   // empty group in tail keeps wait arithmetic uniform

        uint32_t aB = sb + (it & (STAGES - 1)) * STAGE_BYTES;
        uint32_t bB = aB + TBM * 64;

#pragma unroll
        for (int kk = 0; kk < 2; kk++) {   // two k16 steps per BK=32
            uint32_t af[2][4];
            uint32_t bf[4][4];
#pragma unroll
            for (int mt = 0; mt < 2; mt++) {
                int r = raBase + mt * 16;
                int g = kk * 2 + gaSel;
                uint32_t addr = aB + (uint32_t)(r * 64 + ((g ^ ((r >> 1) & 3)) << 4));
                asm volatile("ldmatrix.sync.aligned.m8n8.x4.shared.b16 {%0,%1,%2,%3}, [%4];\n"
                             : "=r"(af[mt][0]), "=r"(af[mt][1]), "=r"(af[mt][2]), "=r"(af[mt][3])
                             : "r"(addr));
            }
#pragma unroll
            for (int nt = 0; nt < 4; nt++) {
                int r = rbBase + nt * 16;
                int g = kk * 2 + gbSel;
                uint32_t addr = bB + (uint32_t)(r * 64 + ((g ^ ((r >> 1) & 3)) << 4));
                asm volatile("ldmatrix.sync.aligned.m8n8.x4.shared.b16 {%0,%1,%2,%3}, [%4];\n"
                             : "=r"(bf[nt][0]), "=r"(bf[nt][1]), "=r"(bf[nt][2]), "=r"(bf[nt][3])
                             : "r"(addr));
            }
            // 16 independent MMAs per k16 step.
            // bf[nt][0..3] = (n-lo,k-lo),(n-lo,k-hi),(n-hi,k-lo),(n-hi,k-hi):
            // pair for sub-block h is (bf[nt][h*2], bf[nt][h*2+1]).
#pragma unroll
            for (int mt = 0; mt < 2; mt++)
#pragma unroll
                for (int nt = 0; nt < 4; nt++)
#pragma unroll
                    for (int h = 0; h < 2; h++) {
                        asm volatile(
                            "mma.sync.aligned.m16n8k16.row.col.f32.bf16.bf16.f32 "
                            "{%0,%1,%2,%3}, {%4,%5,%6,%7}, {%8,%9}, {%0,%1,%2,%3};\n"
                            : "+f"(acc[mt][nt * 2 + h][0]), "+f"(acc[mt][nt * 2 + h][1]),
                              "+f"(acc[mt][nt * 2 + h][2]), "+f"(acc[mt][nt * 2 + h][3])
                            : "r"(af[mt][0]), "r"(af[mt][1]), "r"(af[mt][2]), "r"(af[mt][3]),
                              "r"(bf[nt][h * 2]), "r"(bf[nt][h * 2 + 1]));
                    }
        }
    }

    // write split-partial tile (plain float2 stores, no atomics)
    float* part = g_part[pair * SPLITS + split];
#pragma unroll
    for (int mt = 0; mt < 2; mt++)
#pragma unroll
        for (int nt = 0; nt < 4; nt++)
#pragma unroll
            for (int h = 0; h < 2; h++) {
                int r0 = wm * 32 + mt * 16 + (lane >> 2);
                int c  = wn * 64 + nt * 16 + h * 8 + ((lane & 3) << 1);
                float* a4 = acc[mt][nt * 2 + h];
                *(float2*)(part + r0 * TBM + c)       = make_float2(a4[0], a4[1]);
                *(float2*)(part + (r0 + 8) * TBM + c) = make_float2(a4[2], a4[3]);
            }

    __threadfence();   // publish partial tile
    if (tid == 0) s_prev = atomicAdd(&g_tile_cnt[pair], 1u);
    __syncthreads();

    if (s_prev == SPLITS - 1) {   // last split: combine, square, accumulate
        __threadfence();
        const float invD = 1.0f / (float)DDIM;
        const float* p0 = g_part[pair * SPLITS + 0];
        const float* p1 = g_part[pair * SPLITS + 1];
        const float* p2 = g_part[pair * SPLITS + 2];
        const float* p3 = g_part[pair * SPLITS + 3];
        float ss = 0.0f;
        for (int idx = tid; idx < TBM * TBM; idx += 256) {
            int r = idx >> 7, c = idx & 127;
            int gi = bi * TBM + r, gj = bj * TBM + c;
            if (gi < gj) {   // pad rows/cols are exact zeros
                float v = (p0[idx] + p1[idx] + p2[idx] + p3[idx]) * invD;
                ss += v * v;
            }
        }
#pragma unroll
        for (int o = 16; o > 0; o >>= 1) ss += __shfl_xor_sync(0xffffffffu, ss, o);
        if (lane == 0) s_red[warp] = ss;
        __syncthreads();
        if (tid == 0) {
            float bs = 0.0f;
#pragma unroll
            for (int w2 = 0; w2 < 8; w2++) bs += s_red[w2];
            atomicAdd(&g_sumsq, bs);
            __threadfence();
            unsigned p = atomicAdd(&g_pairs_done, 1u);
            int T = (k + TBM - 1) / TBM;
            unsigned tot = (unsigned)(T * (T + 1) / 2);
            if (p == tot - 1) {   // last tile overall: write the loss
                float total = atomicAdd(&g_sumsq, 0.0f);
                long long np = (long long)k * (k - 1) / 2;
                out[0] = (np > 0) ? (total / (float)np) : 0.0f;
            }
        }
    }
}

extern "C" void kernel_launch(void* const* d_in, const int* in_sizes, int n_in,
                              void* d_out, int out_size) {
    const float* w    = (const float*)d_in[0];  // [2048,1024,3,3] fp32
    const float* mask = (const float*)d_in[1];  // [2048,1,1,1]   fp32
    float* out = (float*)d_out;

    static bool attr_set = false;
    if (!attr_set) {
        cudaFuncSetAttribute(gram_kernel,
                             cudaFuncAttributeMaxDynamicSharedMemorySize, DSMEM_BYTES);
        attr_set = true;
    }

    scan_mask_kernel<<<1, 1024>>>(mask, out);
    normalize_kernel<<<NROWS, 256>>>(w);
    gram_kernel<<<NPAIR * SPLITS, 256, DSMEM_BYTES>>>(out);
}